// round 15
// baseline (speedup 1.0000x reference)
#include <cuda_runtime.h>
#include <cuda_fp16.h>
#include <cstdint>

// Problem constants
#define BATCH 16
#define NTOK  8192
#define FIN   256
#define FOUT  256
#define EPSBN 1e-5f
#define CTAS_PER_BATCH 64        // NTOK / BM

// Hybrid warp-specialized tiling: CTA 128x256.
//  warps 0-7  : tensor, rows 0..95  (warp tile 48x64, 2m x 4n)
//  warps 8-11 : HFMA2,  rows 96..127 (one warp per SMSP, 8 rows x 256 cols)
#define BM 128
#define BN 256
#define BK 32
#define NCHUNK (FIN / BK)        // 8
#define THREADS 384
#define LDA32 36                 // fp32 A stage row stride (floats)
#define LDKH  40                 // fp16 row stride (halves)
#define A_STAGE_BYTES (BM * LDA32 * 4)            // 18432
#define B_STAGE_BYTES (BN * LDKH * 2)             // 20480
#define STAGE_BYTES   (A_STAGE_BYTES + B_STAGE_BYTES)   // 38912
#define NSTAGE 4
#define AH_BYTES      (BM * LDKH * 2)             // 10240
#define AH_HALVES     (BM * LDKH)
#define SMEM_ALLOC    (NSTAGE * STAGE_BYTES + 2 * AH_BYTES)  // 176128

// device-global scratch (no allocations allowed)
__device__ __half g_Wh  [FOUT * FIN];
__device__ float  g_sum  [BATCH * FOUT];
__device__ float  g_sumsq[BATCH * FOUT];
__device__ int    g_count[BATCH];

// ---------------------------------------------------------------------------
__device__ __forceinline__ uint32_t s2u(const void* p) {
    uint32_t a;
    asm("{ .reg .u64 t; cvta.to.shared.u64 t, %1; cvt.u32.u64 %0, t; }"
        : "=r"(a) : "l"(p));
    return a;
}
__device__ __forceinline__ void cp16(uint32_t saddr, const void* g) {
    asm volatile("cp.async.cg.shared.global [%0], [%1], 16;"
                 :: "r"(saddr), "l"(g));
}
__device__ __forceinline__ void mma_f16acc(uint32_t* c, const uint32_t* a,
                                           const uint32_t* b) {
    asm volatile(
        "mma.sync.aligned.m16n8k16.row.col.f16.f16.f16.f16 "
        "{%0,%1}, {%2,%3,%4,%5}, {%6,%7}, {%0,%1};"
        : "+r"(c[0]), "+r"(c[1])
        : "r"(a[0]), "r"(a[1]), "r"(a[2]), "r"(a[3]), "r"(b[0]), "r"(b[1]));
}
__device__ __forceinline__ void ldsm_x4(uint32_t* r, uint32_t saddr) {
    asm volatile("ldmatrix.sync.aligned.m8n8.x4.shared.b16 {%0,%1,%2,%3}, [%4];"
                 : "=r"(r[0]), "=r"(r[1]), "=r"(r[2]), "=r"(r[3]) : "r"(saddr));
}
__device__ __forceinline__ void ldsm_x2(uint32_t* r, uint32_t saddr) {
    asm volatile("ldmatrix.sync.aligned.m8n8.x2.shared.b16 {%0,%1}, [%2];"
                 : "=r"(r[0]), "=r"(r[1]) : "r"(saddr));
}
__device__ __forceinline__ __half2 u2h2(uint32_t u) {
    return *reinterpret_cast<__half2*>(&u);
}

// ---------------------------------------------------------------------------
// Kernel A: W fp32 -> fp16 + zero stats/counters (one launch)
// ---------------------------------------------------------------------------
__global__ void prep_kernel(const float* __restrict__ W) {
    int i = blockIdx.x * blockDim.x + threadIdx.x;      // 0 .. 32767
    if (i < FOUT * FIN / 2) {
        float2 f = reinterpret_cast<const float2*>(W)[i];
        reinterpret_cast<__half2*>(g_Wh)[i] = __floats2half2_rn(f.x, f.y);
    }
    if (i < BATCH * FOUT) { g_sum[i] = 0.0f; g_sumsq[i] = 0.0f; }
    if (i < BATCH) g_count[i] = 0;
}

// ---------------------------------------------------------------------------
// Kernel B: fused hybrid GEMM + BatchNorm, warp-specialized tensor/HFMA2.
// grid = BATCH * 64 (batch = bx>>6 contiguous), block = 384
// ---------------------------------------------------------------------------
__global__ __launch_bounds__(THREADS, 1)
void gemm_bn_kernel(const float* __restrict__ x,
                    const float* __restrict__ bias,
                    const float* __restrict__ gamma,
                    const float* __restrict__ beta,
                    float* __restrict__ out)
{
    extern __shared__ char smem[];
    const uint32_t smem_u = s2u(smem);
    const uint32_t ah_u   = smem_u + NSTAGE * STAGE_BYTES;

    const int tid  = threadIdx.x;
    const int lane = tid & 31;
    const int wid  = tid >> 5;           // 0..11

    const int bx = blockIdx.x;
    const int mt = bx & 63;
    const int b  = bx >> 6;
    const int m0 = mt * BM;

    const float* xb = x + ((size_t)b * NTOK + m0) * FIN;

    const bool is_tensor = (wid < 8);
    const int warp_m = wid >> 2;         // tensor: 0..1 -> 48-row slice
    const int warp_n = wid & 3;          // tensor: 0..3 -> 64-col slice
    const int fw     = wid - 8;          // fma warp id 0..3
    const int frow0  = 96 + fw * 8;      // fma warp's 8 rows

    // tensor ldmatrix lane address components
    const int j8  = lane >> 3;
    const int lr8 = lane & 7;
    const uint32_t a_lane_off =
        (uint32_t)(((warp_m * 48) + (j8 & 1) * 8 + lr8) * LDKH + (j8 >> 1) * 8) * 2u;
    const uint32_t b_lane_off =
        (uint32_t)(((warp_n * 64) + lr8) * LDKH + (j8 & 1) * 8) * 2u;

    // tensor accumulators: 2 fp16 chains x 3 mi x 8 ni
    uint32_t accL[3][8][2], accH[3][8][2];
    // fma accumulators: 8 rows x 8 cols fp32 (cols = lane + 32*jj)
    float facc[8][8];
    if (is_tensor) {
#pragma unroll
        for (int mi = 0; mi < 3; mi++)
#pragma unroll
            for (int ni = 0; ni < 8; ni++) {
                accL[mi][ni][0] = 0u; accL[mi][ni][1] = 0u;
                accH[mi][ni][0] = 0u; accH[mi][ni][1] = 0u;
            }
    } else {
#pragma unroll
        for (int r = 0; r < 8; r++)
#pragma unroll
            for (int jj = 0; jj < 8; jj++) facc[r][jj] = 0.0f;
    }

    // stage loader: A fp32 (1024 granules) + B fp16 (1024 granules), 384 thr
    auto load_stage = [&](int c, int s) {
        const uint32_t abase = smem_u + (uint32_t)(s * STAGE_BYTES);
        const uint32_t bbase = abase + A_STAGE_BYTES;
        const int k0 = c * BK;
#pragma unroll
        for (int i = 0; i < 3; i++) {
            int idx = tid + i * THREADS;
            if (idx < 1024) {
                int r = idx >> 3, gi = idx & 7;
                cp16(abase + (uint32_t)(r * LDA32 + gi * 4) * 4u,
                     xb + (size_t)r * FIN + k0 + gi * 4);
            }
        }
#pragma unroll
        for (int i = 0; i < 3; i++) {
            int idx = tid + i * THREADS;
            if (idx < 1024) {
                int r = idx >> 2, gi = idx & 3;
                cp16(bbase + (uint32_t)(r * LDKH + gi * 8) * 2u,
                     g_Wh + (size_t)r * FIN + k0 + gi * 8);
            }
        }
    };

    // convert fp32 A of stage c -> fp16 Ah buffer (self-loaded granules)
    auto convert_A = [&](int c, int buf) {
        const float* Sa = (const float*)(smem + (c & (NSTAGE - 1)) * STAGE_BYTES);
        const uint32_t abase = ah_u + (uint32_t)(buf * AH_BYTES);
#pragma unroll
        for (int i = 0; i < 3; i++) {
            int idx = tid + i * THREADS;
            if (idx < 1024) {
                int r = idx >> 3, c4 = idx & 7;
                float4 v = *(const float4*)(Sa + r * LDA32 + c4 * 4);
                __half2 h0 = __floats2half2_rn(v.x, v.y);
                __half2 h1 = __floats2half2_rn(v.z, v.w);
                asm volatile("st.shared.v2.b32 [%0], {%1, %2};"
                    :: "r"(abase + (uint32_t)(r * LDKH + c4 * 4) * 2u),
                       "r"(*(const uint32_t*)&h0), "r"(*(const uint32_t*)&h1));
            }
        }
    };

    // prologue: stages 0,1,2 in flight; stage 0 converted into Ah[0]
    load_stage(0, 0);
    asm volatile("cp.async.commit_group;" ::: "memory");
    load_stage(1, 1);
    asm volatile("cp.async.commit_group;" ::: "memory");
    load_stage(2, 2);
    asm volatile("cp.async.commit_group;" ::: "memory");
    asm volatile("cp.async.wait_group 2;" ::: "memory");
    convert_A(0, 0);

    for (int c = 0; c < NCHUNK; c++) {
        __syncthreads();   // publishes Ah[c&1] + stage c; frees buf (c-1)&3

        if (c + 3 < NCHUNK) {
            load_stage(c + 3, (c + 3) & (NSTAGE - 1));
            asm volatile("cp.async.commit_group;" ::: "memory");
        }

        if (is_tensor) {
            // ---- tensor phase: rows 0..95 ----
            uint32_t (*acc)[8][2] = (c < 4) ? accL : accH;
            const uint32_t abase = ah_u + (uint32_t)((c & 1) * AH_BYTES) + a_lane_off;
            const uint32_t bbase = smem_u + (uint32_t)((c & (NSTAGE - 1)) * STAGE_BYTES)
                                   + A_STAGE_BYTES + b_lane_off;
#pragma unroll
            for (int ks = 0; ks < 2; ks++) {
                const uint32_t koff = (uint32_t)(ks * 16) * 2u;
                uint32_t af[3][4];
#pragma unroll
                for (int mi = 0; mi < 3; mi++)
                    ldsm_x4(af[mi], abase + (uint32_t)(mi * 16 * LDKH) * 2u + koff);
                uint32_t bf[8][2];
#pragma unroll
                for (int ni = 0; ni < 8; ni++)
                    ldsm_x2(bf[ni], bbase + (uint32_t)(ni * 8 * LDKH) * 2u + koff);
#pragma unroll
                for (int mi = 0; mi < 3; mi++)
#pragma unroll
                    for (int ni = 0; ni < 8; ni++)
                        mma_f16acc(acc[mi][ni], af[mi], bf[ni]);
            }
        } else {
            // ---- fma phase: rows 96..127 on the fma pipe (HFMA2) ----
            const __half* Ab = (const __half*)(smem + NSTAGE * STAGE_BYTES
                                + (c & 1) * AH_BYTES) + frow0 * LDKH;
            const __half* Bs = (const __half*)(smem
                                + (c & (NSTAGE - 1)) * STAGE_BYTES + A_STAGE_BYTES);
#pragma unroll
            for (int h = 0; h < 2; h++) {        // col halves (reg pressure)
                __half2 c2[8][4];
#pragma unroll
                for (int r = 0; r < 8; r++)
#pragma unroll
                    for (int j = 0; j < 4; j++)
                        c2[r][j] = __floats2half2_rn(0.f, 0.f);
#pragma unroll
                for (int g = 0; g < 8; g++) {    // 8 groups of 4 k (2 kpairs)
                    uint2 av[8];
#pragma unroll
                    for (int r = 0; r < 8; r++)  // broadcast loads
                        av[r] = *(const uint2*)(Ab + r * LDKH + g * 4);
                    uint2 bv[4];
#pragma unroll
                    for (int j = 0; j < 4; j++) {
                        int col = lane + 32 * (4 * h + j);
                        bv[j] = *(const uint2*)(Bs + col * LDKH + g * 4);
                    }
#pragma unroll
                    for (int r = 0; r < 8; r++)
#pragma unroll
                        for (int j = 0; j < 4; j++) {
                            c2[r][j] = __hfma2(u2h2(av[r].x), u2h2(bv[j].x), c2[r][j]);
                            c2[r][j] = __hfma2(u2h2(av[r].y), u2h2(bv[j].y), c2[r][j]);
                        }
                }
#pragma unroll
                for (int r = 0; r < 8; r++)
#pragma unroll
                    for (int j = 0; j < 4; j++) {
                        float2 f = __half22float2(c2[r][j]);
                        facc[r][4 * h + j] += f.x + f.y;
                    }
            }
        }

        // ---- ensure stage c+1 arrived, then convert it into Ah[(c+1)&1] ----
        if (c + 1 < NCHUNK) {
            if (c <= 4)
                asm volatile("cp.async.wait_group 2;" ::: "memory");
            else if (c == 5)
                asm volatile("cp.async.wait_group 1;" ::: "memory");
            else
                asm volatile("cp.async.wait_group 0;" ::: "memory");
            convert_A(c + 1, (c + 1) & 1);
        }
    }

    // ---------------- stats -------------------------------------------------
    const int g2 = lane >> 2;
    const int t  = lane & 3;
    float* gs = &g_sum  [b * FOUT];
    float* gq = &g_sumsq[b * FOUT];
    float* scratch = (float*)smem;      // reuse stage area: [4][512] floats

    if (is_tensor) {
        // rows 0..95: shfl-reduce + global atomics
#pragma unroll
        for (int ni = 0; ni < 8; ni++) {
            const int cc = warp_n * 64 + ni * 8 + 2 * t;
            const float b0v = __ldg(&bias[cc]);
            const float b1v = __ldg(&bias[cc + 1]);
            float s0 = 0.f, s1 = 0.f, q0 = 0.f, q1 = 0.f;
#pragma unroll
            for (int mi = 0; mi < 3; mi++) {
                float2 l0 = __half22float2(*(__half2*)&accL[mi][ni][0]);
                float2 l1 = __half22float2(*(__half2*)&accL[mi][ni][1]);
                float2 h0 = __half22float2(*(__half2*)&accH[mi][ni][0]);
                float2 h1 = __half22float2(*(__half2*)&accH[mi][ni][1]);
                float v0 = l0.x + h0.x + b0v;
                float v1 = l0.y + h0.y + b1v;
                float v2 = l1.x + h1.x + b0v;
                float v3 = l1.y + h1.y + b1v;
                s0 += v0 + v2;  s1 += v1 + v3;
                q0 += v0 * v0 + v2 * v2;
                q1 += v1 * v1 + v3 * v3;
            }
#pragma unroll
            for (int m = 4; m <= 16; m <<= 1) {
                s0 += __shfl_xor_sync(0xFFFFFFFF, s0, m);
                s1 += __shfl_xor_sync(0xFFFFFFFF, s1, m);
                q0 += __shfl_xor_sync(0xFFFFFFFF, q0, m);
                q1 += __shfl_xor_sync(0xFFFFFFFF, q1, m);
            }
            if (lane < 4) {
                atomicAdd(&gs[cc], s0);  atomicAdd(&gs[cc + 1], s1);
                atomicAdd(&gq[cc], q0);  atomicAdd(&gq[cc + 1], q1);
            }
        }
    } else {
        // rows 96..127: add bias into facc, per-col sums into smem scratch
#pragma unroll
        for (int jj = 0; jj < 8; jj++) {
            const int col = lane + 32 * jj;
            const float bv = __ldg(&bias[col]);
            float s = 0.f, q = 0.f;
#pragma unroll
            for (int r = 0; r < 8; r++) {
                float v = facc[r][jj] + bv;
                facc[r][jj] = v;
                s += v;  q += v * v;
            }
            scratch[fw * 512 + col]       = s;
            scratch[fw * 512 + 256 + col] = q;
        }
    }
    __syncthreads();
    if (tid < 256) {     // combine the 4 fma-warp partials -> global atomics
        float s = scratch[tid] + scratch[512 + tid]
                + scratch[1024 + tid] + scratch[1536 + tid];
        float q = scratch[256 + tid] + scratch[768 + tid]
                + scratch[1280 + tid] + scratch[1792 + tid];
        atomicAdd(&gs[tid], s);
        atomicAdd(&gq[tid], q);
    }

    // ---------------- per-batch spin barrier ---------------------------------
    __threadfence();
    __syncthreads();
    if (tid == 0) {
        atomicAdd(&g_count[b], 1);
        while (atomicAdd(&g_count[b], 0) < CTAS_PER_BATCH)
            __nanosleep(100);
    }
    __syncthreads();
    __threadfence();

    // ---------------- normalize from registers, write final output -----------
    const float invN = 1.0f / (float)NTOK;
    float* obase = out + ((size_t)b * NTOK + m0) * FOUT;

    if (is_tensor) {
#pragma unroll
        for (int ni = 0; ni < 8; ni++) {
            const int cc = warp_n * 64 + ni * 8 + 2 * t;
            const float b0v = __ldg(&bias[cc]);
            const float b1v = __ldg(&bias[cc + 1]);
            float mean0 = __ldcg(&gs[cc])     * invN;
            float mean1 = __ldcg(&gs[cc + 1]) * invN;
            float var0  = fmaxf(__ldcg(&gq[cc])     * invN - mean0 * mean0, 0.0f);
            float var1  = fmaxf(__ldcg(&gq[cc + 1]) * invN - mean1 * mean1, 0.0f);
            float sc0 = __ldg(&gamma[cc])     * rsqrtf(var0 + EPSBN);
            float sc1 = __ldg(&gamma[cc + 1]) * rsqrtf(var1 + EPSBN);
            float sh0 = __ldg(&beta[cc])     - mean0 * sc0;
            float sh1 = __ldg(&beta[cc + 1]) - mean1 * sc1;
#pragma unroll
            for (int mi = 0; mi < 3; mi++) {
                int r = warp_m * 48 + mi * 16 + g2;
                float2 l0 = __half22float2(*(__half2*)&accL[mi][ni][0]);
                float2 l1 = __half22float2(*(__half2*)&accL[mi][ni][1]);
                float2 h0 = __half22float2(*(__half2*)&accH[mi][ni][0]);
                float2 h1 = __half22float2(*(__half2*)&accH[mi][ni][1]);
                float v0 = (l0.x + h0.x + b0v) * sc0 + sh0;
                float v1 = (l0.y + h0.y + b1v) * sc1 + sh1;
                float v2 = (l1.x + h1.x + b0v) * sc0 + sh0;
                float v3 = (l1.y + h1.y + b1v) * sc1 + sh1;
                *(float2*)(obase + (size_t)r * FOUT + cc)       = make_float2(v0, v1);
                *(float2*)(obase + (size_t)(r + 8) * FOUT + cc) = make_float2(v2, v3);
            }
        }
    } else {
        float sc[8], sh[8];
#pragma unroll
        for (int jj = 0; jj < 8; jj++) {
            const int col = lane + 32 * jj;
            float mean = __ldcg(&gs[col]) * invN;
            float var  = fmaxf(__ldcg(&gq[col]) * invN - mean * mean, 0.0f);
            sc[jj] = __ldg(&gamma[col]) * rsqrtf(var + EPSBN);
            sh[jj] = __ldg(&beta[col]) - mean * sc[jj];
        }
#pragma unroll
        for (int r = 0; r < 8; r++) {
            float* orow = obase + (size_t)(frow0 + r) * FOUT;
#pragma unroll
            for (int jj = 0; jj < 8; jj++)
                orow[lane + 32 * jj] = facc[r][jj] * sc[jj] + sh[jj];
        }
    }
}

// ---------------------------------------------------------------------------
extern "C" void kernel_launch(void* const* d_in, const int* in_sizes, int n_in,
                              void* d_out, int out_size)
{
    const float* x     = (const float*)d_in[0];
    const float* W     = (const float*)d_in[1];
    const float* bias  = (const float*)d_in[2];
    const float* gamma = (const float*)d_in[3];
    const float* beta  = (const float*)d_in[4];
    float* out = (float*)d_out;

    cudaFuncSetAttribute(gemm_bn_kernel,
                         cudaFuncAttributeMaxDynamicSharedMemorySize,
                         SMEM_ALLOC);

    prep_kernel<<<FOUT * FIN / 2 / 256, 256>>>(W);
    gemm_bn_kernel<<<BATCH * CTAS_PER_BATCH, THREADS, SMEM_ALLOC>>>(
        x, bias, gamma, beta, out);
}

// round 16
// speedup vs baseline: 3.0865x; 3.0865x over previous
#include <cuda_runtime.h>
#include <cuda_fp16.h>
#include <cstdint>

// Problem constants
#define BATCH 16
#define NTOK  8192
#define FIN   256
#define FOUT  256
#define EPSBN 1e-5f
#define CTAS_PER_BATCH 64        // NTOK / BM

// Schedule: 2 batches per 148-slot group; slots 128..147 are dummies.
#define SLOTS_PER_GROUP 148
#define REAL_PER_GROUP  128
#define NGROUPS (BATCH / 2)      // 8

// GEMM tiling: CTA 128x256, warp 64x64, 8 warps (2m x 4n), fp16 MMA fp16 acc
#define BM 128
#define BN 256
#define BK 32
#define NCHUNK (FIN / BK)        // 8
#define THREADS 256
#define LDA32 36                 // fp32 A stage row stride (floats)
#define LDKH  40                 // fp16 row stride (halves)
#define A_STAGE_BYTES (BM * LDA32 * 4)            // 18432
#define B_STAGE_BYTES (BN * LDKH * 2)             // 20480
#define STAGE_BYTES   (A_STAGE_BYTES + B_STAGE_BYTES)   // 38912
#define AH_BYTES      (BM * LDKH * 2)             // 10240
#define SMEM_ALLOC    (3 * STAGE_BYTES + 2 * AH_BYTES)  // 137216

// device-global scratch (no allocations allowed)
__device__ __half g_Wh  [FOUT * FIN];
__device__ float  g_sum  [BATCH * FOUT];
__device__ float  g_sumsq[BATCH * FOUT];
__device__ int    g_count[BATCH];

// ---------------------------------------------------------------------------
__device__ __forceinline__ uint32_t s2u(const void* p) {
    uint32_t a;
    asm("{ .reg .u64 t; cvta.to.shared.u64 t, %1; cvt.u32.u64 %0, t; }"
        : "=r"(a) : "l"(p));
    return a;
}
__device__ __forceinline__ void cp16(uint32_t saddr, const void* g) {
    asm volatile("cp.async.cg.shared.global [%0], [%1], 16;"
                 :: "r"(saddr), "l"(g));
}
__device__ __forceinline__ void mma_f16acc(uint32_t* c, const uint32_t* a,
                                           const uint32_t* b) {
    asm volatile(
        "mma.sync.aligned.m16n8k16.row.col.f16.f16.f16.f16 "
        "{%0,%1}, {%2,%3,%4,%5}, {%6,%7}, {%0,%1};"
        : "+r"(c[0]), "+r"(c[1])
        : "r"(a[0]), "r"(a[1]), "r"(a[2]), "r"(a[3]), "r"(b[0]), "r"(b[1]));
}

// ---------------------------------------------------------------------------
// Kernel A: W fp32 -> fp16 + zero stats/counters (one launch)
// ---------------------------------------------------------------------------
__global__ void prep_kernel(const float* __restrict__ W) {
    int i = blockIdx.x * blockDim.x + threadIdx.x;      // 0 .. 32767
    if (i < FOUT * FIN / 2) {
        float2 f = reinterpret_cast<const float2*>(W)[i];
        reinterpret_cast<__half2*>(g_Wh)[i] = __floats2half2_rn(f.x, f.y);
    }
    if (i < BATCH * FOUT) { g_sum[i] = 0.0f; g_sumsq[i] = 0.0f; }
    if (i < BATCH) g_count[i] = 0;
}

// ---------------------------------------------------------------------------
// Kernel B: fused GEMM + BatchNorm (identical mainloop to the 139.4us best);
// NEW: wave-aligned batch schedule. grid = 8 * 148. slot >= 128 exits.
// batch = 2*group + (slot>=64)  ->  all 64 CTAs of a batch in one wave.
// ---------------------------------------------------------------------------
__global__ __launch_bounds__(THREADS, 1)
void gemm_bn_kernel(const float* __restrict__ x,
                    const float* __restrict__ bias,
                    const float* __restrict__ gamma,
                    const float* __restrict__ beta,
                    float* __restrict__ out)
{
    const int bx   = blockIdx.x;
    const int grp  = bx / SLOTS_PER_GROUP;
    const int slot = bx % SLOTS_PER_GROUP;
    if (slot >= REAL_PER_GROUP) return;      // dummy: retire, free the SM

    extern __shared__ char smem[];
    const uint32_t smem_u = s2u(smem);
    __half* Ah = (__half*)(smem + 3 * STAGE_BYTES);

    const int tid  = threadIdx.x;
    const int lane = tid & 31;
    const int wid  = tid >> 5;

    const int b  = grp * 2 + (slot >> 6);
    const int mt = slot & 63;
    const int m0 = mt * BM;

    const float* xb = x + ((size_t)b * NTOK + m0) * FIN;

    const int warp_m = wid >> 2;         // 0..1 -> 64-row slice
    const int warp_n = wid & 3;          // 0..3 -> 64-col slice
    const int g    = lane >> 2;          // 0..7
    const int t    = lane & 3;           // 0..3

    // two independent fp16 accumulator chains (chunks 0-3 and 4-7)
    uint32_t accL[4][8][2], accH[4][8][2];
#pragma unroll
    for (int mi = 0; mi < 4; mi++)
#pragma unroll
        for (int ni = 0; ni < 8; ni++) {
            accL[mi][ni][0] = 0u; accL[mi][ni][1] = 0u;
            accH[mi][ni][0] = 0u; accH[mi][ni][1] = 0u;
        }

    auto load_stage = [&](int c, int s) {
        const uint32_t abase = smem_u + (uint32_t)(s * STAGE_BYTES);
        const uint32_t bbase = abase + A_STAGE_BYTES;
        const int k0 = c * BK;
#pragma unroll
        for (int i = 0; i < 4; i++) {        // A fp32: 128 rows x 8 granules
            int idx = tid + i * THREADS;
            int r = idx >> 3, gi = idx & 7;
            cp16(abase + (uint32_t)(r * LDA32 + gi * 4) * 4u,
                 xb + (size_t)r * FIN + k0 + gi * 4);
        }
#pragma unroll
        for (int i = 0; i < 4; i++) {        // B fp16: 256 rows x 4 granules
            int idx = tid + i * THREADS;
            int r = idx >> 2, gi = idx & 3;
            cp16(bbase + (uint32_t)(r * LDKH + gi * 8) * 2u,
                 g_Wh + (size_t)r * FIN + k0 + gi * 8);
        }
    };

    load_stage(0, 0);
    asm volatile("cp.async.commit_group;" ::: "memory");
    load_stage(1, 1);
    asm volatile("cp.async.commit_group;" ::: "memory");

    for (int c = 0; c < NCHUNK; c++) {
        if (c + 1 < NCHUNK)
            asm volatile("cp.async.wait_group 1;" ::: "memory");
        else
            asm volatile("cp.async.wait_group 0;" ::: "memory");
        __syncthreads();   // stage c visible; Ah free (prev MMA done)

        if (c + 2 < NCHUNK) {
            load_stage(c + 2, (c + 2) % 3);
            asm volatile("cp.async.commit_group;" ::: "memory");
        }

        // convert A fp32 stage -> fp16 tile
        {
            const float* Sa = (const float*)(smem + (c % 3) * STAGE_BYTES);
#pragma unroll
            for (int i = 0; i < 4; i++) {
                int idx = tid + i * THREADS;
                int r = idx >> 3, c4 = idx & 7;
                float4 v = *(const float4*)(Sa + r * LDA32 + c4 * 4);
                __half2 h0 = __floats2half2_rn(v.x, v.y);
                __half2 h1 = __floats2half2_rn(v.z, v.w);
                uint2 pk = make_uint2(*(uint32_t*)&h0, *(uint32_t*)&h1);
                *(uint2*)(Ah + r * LDKH + c4 * 4) = pk;
            }
        }
        __syncthreads();

        uint32_t (*acc)[8][2] = (c < 4) ? accL : accH;

        const __half* Aw = Ah + (warp_m * 64) * LDKH;
        const __half* Bw = (const __half*)(smem + (c % 3) * STAGE_BYTES
                             + A_STAGE_BYTES) + (warp_n * 64) * LDKH;
#pragma unroll
        for (int ks = 0; ks < 2; ks++) {
            const int kk = ks * 16;
            uint32_t af[4][4];
#pragma unroll
            for (int mi = 0; mi < 4; mi++) {
                int r = mi * 16 + g;
                af[mi][0] = *(const uint32_t*)&Aw[ r      * LDKH + kk + 2 * t    ];
                af[mi][1] = *(const uint32_t*)&Aw[(r + 8) * LDKH + kk + 2 * t    ];
                af[mi][2] = *(const uint32_t*)&Aw[ r      * LDKH + kk + 2 * t + 8];
                af[mi][3] = *(const uint32_t*)&Aw[(r + 8) * LDKH + kk + 2 * t + 8];
            }
            uint32_t bf[8][2];
#pragma unroll
            for (int ni = 0; ni < 8; ni++) {
                int n = ni * 8 + g;
                bf[ni][0] = *(const uint32_t*)&Bw[n * LDKH + kk + 2 * t    ];
                bf[ni][1] = *(const uint32_t*)&Bw[n * LDKH + kk + 2 * t + 8];
            }
#pragma unroll
            for (int mi = 0; mi < 4; mi++)
#pragma unroll
                for (int ni = 0; ni < 8; ni++)
                    mma_f16acc(acc[mi][ni], af[mi], bf[ni]);
        }
    }

    // ---------------- stats: column sums/sumsq -> global atomics -------------
    float* gs = &g_sum  [b * FOUT];
    float* gq = &g_sumsq[b * FOUT];
#pragma unroll
    for (int ni = 0; ni < 8; ni++) {
        const int cc = warp_n * 64 + ni * 8 + 2 * t;
        const float b0v = __ldg(&bias[cc]);
        const float b1v = __ldg(&bias[cc + 1]);
        float s0 = 0.f, s1 = 0.f, q0 = 0.f, q1 = 0.f;
#pragma unroll
        for (int mi = 0; mi < 4; mi++) {
            float2 l0 = __half22float2(*(__half2*)&accL[mi][ni][0]);
            float2 l1 = __half22float2(*(__half2*)&accL[mi][ni][1]);
            float2 h0 = __half22float2(*(__half2*)&accH[mi][ni][0]);
            float2 h1 = __half22float2(*(__half2*)&accH[mi][ni][1]);
            float v0 = l0.x + h0.x + b0v;
            float v1 = l0.y + h0.y + b1v;
            float v2 = l1.x + h1.x + b0v;
            float v3 = l1.y + h1.y + b1v;
            s0 += v0 + v2;  s1 += v1 + v3;
            q0 += v0 * v0 + v2 * v2;
            q1 += v1 * v1 + v3 * v3;
        }
#pragma unroll
        for (int m = 4; m <= 16; m <<= 1) {
            s0 += __shfl_xor_sync(0xFFFFFFFF, s0, m);
            s1 += __shfl_xor_sync(0xFFFFFFFF, s1, m);
            q0 += __shfl_xor_sync(0xFFFFFFFF, q0, m);
            q1 += __shfl_xor_sync(0xFFFFFFFF, q1, m);
        }
        if (lane < 4) {
            atomicAdd(&gs[cc], s0);  atomicAdd(&gs[cc + 1], s1);
            atomicAdd(&gq[cc], q0);  atomicAdd(&gq[cc + 1], q1);
        }
    }

    // ---------------- per-batch spin barrier (batch within one wave) ---------
    __threadfence();
    __syncthreads();
    if (tid == 0) {
        atomicAdd(&g_count[b], 1);
        while (atomicAdd(&g_count[b], 0) < CTAS_PER_BATCH)
            __nanosleep(100);
    }
    __syncthreads();
    __threadfence();

    // ---------------- normalize from registers, write final output -----------
    const float invN = 1.0f / (float)NTOK;
    float* obase = out + ((size_t)b * NTOK + m0) * FOUT;

#pragma unroll
    for (int ni = 0; ni < 8; ni++) {
        const int cc = warp_n * 64 + ni * 8 + 2 * t;
        const float b0v = __ldg(&bias[cc]);
        const float b1v = __ldg(&bias[cc + 1]);
        float mean0 = __ldcg(&gs[cc])     * invN;
        float mean1 = __ldcg(&gs[cc + 1]) * invN;
        float var0  = fmaxf(__ldcg(&gq[cc])     * invN - mean0 * mean0, 0.0f);
        float var1  = fmaxf(__ldcg(&gq[cc + 1]) * invN - mean1 * mean1, 0.0f);
        float sc0 = __ldg(&gamma[cc])     * rsqrtf(var0 + EPSBN);
        float sc1 = __ldg(&gamma[cc + 1]) * rsqrtf(var1 + EPSBN);
        float sh0 = __ldg(&beta[cc])     - mean0 * sc0;
        float sh1 = __ldg(&beta[cc + 1]) - mean1 * sc1;
#pragma unroll
        for (int mi = 0; mi < 4; mi++) {
            int r = warp_m * 64 + mi * 16 + g;
            float2 l0 = __half22float2(*(__half2*)&accL[mi][ni][0]);
            float2 l1 = __half22float2(*(__half2*)&accL[mi][ni][1]);
            float2 h0 = __half22float2(*(__half2*)&accH[mi][ni][0]);
            float2 h1 = __half22float2(*(__half2*)&accH[mi][ni][1]);
            float v0 = (l0.x + h0.x + b0v) * sc0 + sh0;
            float v1 = (l0.y + h0.y + b1v) * sc1 + sh1;
            float v2 = (l1.x + h1.x + b0v) * sc0 + sh0;
            float v3 = (l1.y + h1.y + b1v) * sc1 + sh1;
            *(float2*)(obase + (size_t)r * FOUT + cc)       = make_float2(v0, v1);
            *(float2*)(obase + (size_t)(r + 8) * FOUT + cc) = make_float2(v2, v3);
        }
    }
}

// ---------------------------------------------------------------------------
extern "C" void kernel_launch(void* const* d_in, const int* in_sizes, int n_in,
                              void* d_out, int out_size)
{
    const float* x     = (const float*)d_in[0];
    const float* W     = (const float*)d_in[1];
    const float* bias  = (const float*)d_in[2];
    const float* gamma = (const float*)d_in[3];
    const float* beta  = (const float*)d_in[4];
    float* out = (float*)d_out;

    cudaFuncSetAttribute(gemm_bn_kernel,
                         cudaFuncAttributeMaxDynamicSharedMemorySize,
                         SMEM_ALLOC);

    prep_kernel<<<FOUT * FIN / 2 / 256, 256>>>(W);
    gemm_bn_kernel<<<NGROUPS * SLOTS_PER_GROUP, THREADS, SMEM_ALLOC>>>(
        x, bias, gamma, beta, out);
}

// round 17
// speedup vs baseline: 3.1683x; 1.0265x over previous
#include <cuda_runtime.h>
#include <cuda_fp16.h>
#include <cstdint>

// Problem constants
#define BATCH 16
#define NTOK  8192
#define FIN   256
#define FOUT  256
#define EPSBN 1e-5f
#define CTAS_PER_BATCH 64        // NTOK / BM

// GEMM tiling: CTA 128x256, warp 64x64, 8 warps (2m x 4n), fp16 MMA fp16 acc
#define BM 128
#define BN 256
#define BK 32
#define NCHUNK (FIN / BK)        // 8
#define THREADS 256
#define LDA32 36                 // fp32 A stage row stride (floats)
#define LDKH  40                 // fp16 row stride (halves)
#define A_STAGE_BYTES (BM * LDA32 * 4)            // 18432
#define B_STAGE_BYTES (BN * LDKH * 2)             // 20480
#define STAGE_BYTES   (A_STAGE_BYTES + B_STAGE_BYTES)   // 38912
#define AH_BYTES      (BM * LDKH * 2)             // 10240
#define SMEM_ALLOC    (3 * STAGE_BYTES + 2 * AH_BYTES)  // 137216

// device-global scratch (no allocations allowed)
__device__ __half g_Wh  [FOUT * FIN];
__device__ float  g_sum  [BATCH * FOUT];
__device__ float  g_sumsq[BATCH * FOUT];
__device__ int    g_count[BATCH];

// ---------------------------------------------------------------------------
__device__ __forceinline__ uint32_t s2u(const void* p) {
    uint32_t a;
    asm("{ .reg .u64 t; cvta.to.shared.u64 t, %1; cvt.u32.u64 %0, t; }"
        : "=r"(a) : "l"(p));
    return a;
}
__device__ __forceinline__ void cp16(uint32_t saddr, const void* g) {
    asm volatile("cp.async.cg.shared.global [%0], [%1], 16;"
                 :: "r"(saddr), "l"(g));
}
__device__ __forceinline__ void mma_f16acc(uint32_t* c, const uint32_t* a,
                                           const uint32_t* b) {
    asm volatile(
        "mma.sync.aligned.m16n8k16.row.col.f16.f16.f16.f16 "
        "{%0,%1}, {%2,%3,%4,%5}, {%6,%7}, {%0,%1};"
        : "+r"(c[0]), "+r"(c[1])
        : "r"(a[0]), "r"(a[1]), "r"(a[2]), "r"(a[3]), "r"(b[0]), "r"(b[1]));
}
__device__ __forceinline__ void stcs2(float* p, float a, float b) {
    asm volatile("st.global.cs.v2.f32 [%0], {%1, %2};"
                 :: "l"(p), "f"(a), "f"(b) : "memory");
}

// ---------------------------------------------------------------------------
// Kernel A: W fp32 -> fp16 + zero stats/counters (one launch)
// ---------------------------------------------------------------------------
__global__ void prep_kernel(const float* __restrict__ W) {
    int i = blockIdx.x * blockDim.x + threadIdx.x;      // 0 .. 32767
    if (i < FOUT * FIN / 2) {
        float2 f = reinterpret_cast<const float2*>(W)[i];
        reinterpret_cast<__half2*>(g_Wh)[i] = __floats2half2_rn(f.x, f.y);
    }
    if (i < BATCH * FOUT) { g_sum[i] = 0.0f; g_sumsq[i] = 0.0f; }
    if (i < BATCH) g_count[i] = 0;
}

// ---------------------------------------------------------------------------
// Kernel B: fused GEMM + BatchNorm (best-measured R8 mainloop).
// grid = BATCH * 64 (batch = bx>>6 contiguous), block = 256
// ---------------------------------------------------------------------------
__global__ __launch_bounds__(THREADS, 1)
void gemm_bn_kernel(const float* __restrict__ x,
                    const float* __restrict__ bias,
                    const float* __restrict__ gamma,
                    const float* __restrict__ beta,
                    float* __restrict__ out)
{
    extern __shared__ char smem[];
    const uint32_t smem_u = s2u(smem);
    __half* Ah = (__half*)(smem + 3 * STAGE_BYTES);

    const int tid  = threadIdx.x;
    const int lane = tid & 31;
    const int wid  = tid >> 5;
    const int g    = lane >> 2;          // 0..7
    const int t    = lane & 3;           // 0..3

    const int bx = blockIdx.x;
    const int mt = bx & 63;
    const int b  = bx >> 6;
    const int m0 = mt * BM;

    const float* xb = x + ((size_t)b * NTOK + m0) * FIN;

    const int warp_m = wid >> 2;         // 0..1 -> 64-row slice
    const int warp_n = wid & 3;          // 0..3 -> 64-col slice

    // two independent fp16 accumulator chains (chunks 0-3 and 4-7)
    uint32_t accL[4][8][2], accH[4][8][2];
#pragma unroll
    for (int mi = 0; mi < 4; mi++)
#pragma unroll
        for (int ni = 0; ni < 8; ni++) {
            accL[mi][ni][0] = 0u; accL[mi][ni][1] = 0u;
            accH[mi][ni][0] = 0u; accH[mi][ni][1] = 0u;
        }

    auto load_stage = [&](int c, int s) {
        const uint32_t abase = smem_u + (uint32_t)(s * STAGE_BYTES);
        const uint32_t bbase = abase + A_STAGE_BYTES;
        const int k0 = c * BK;
#pragma unroll
        for (int i = 0; i < 4; i++) {        // A fp32: 128 rows x 8 granules
            int idx = tid + i * THREADS;
            int r = idx >> 3, gi = idx & 7;
            cp16(abase + (uint32_t)(r * LDA32 + gi * 4) * 4u,
                 xb + (size_t)r * FIN + k0 + gi * 4);
        }
#pragma unroll
        for (int i = 0; i < 4; i++) {        // B fp16: 256 rows x 4 granules
            int idx = tid + i * THREADS;
            int r = idx >> 2, gi = idx & 3;
            cp16(bbase + (uint32_t)(r * LDKH + gi * 8) * 2u,
                 g_Wh + (size_t)r * FIN + k0 + gi * 8);
        }
    };

    load_stage(0, 0);
    asm volatile("cp.async.commit_group;" ::: "memory");
    load_stage(1, 1);
    asm volatile("cp.async.commit_group;" ::: "memory");

    for (int c = 0; c < NCHUNK; c++) {
        if (c + 1 < NCHUNK)
            asm volatile("cp.async.wait_group 1;" ::: "memory");
        else
            asm volatile("cp.async.wait_group 0;" ::: "memory");
        __syncthreads();   // stage c visible; Ah free (prev MMA done)

        if (c + 2 < NCHUNK) {
            load_stage(c + 2, (c + 2) % 3);
            asm volatile("cp.async.commit_group;" ::: "memory");
        }

        // convert A fp32 stage -> fp16 tile
        {
            const float* Sa = (const float*)(smem + (c % 3) * STAGE_BYTES);
#pragma unroll
            for (int i = 0; i < 4; i++) {
                int idx = tid + i * THREADS;
                int r = idx >> 3, c4 = idx & 7;
                float4 v = *(const float4*)(Sa + r * LDA32 + c4 * 4);
                __half2 h0 = __floats2half2_rn(v.x, v.y);
                __half2 h1 = __floats2half2_rn(v.z, v.w);
                uint2 pk = make_uint2(*(uint32_t*)&h0, *(uint32_t*)&h1);
                *(uint2*)(Ah + r * LDKH + c4 * 4) = pk;
            }
        }
        __syncthreads();

        uint32_t (*acc)[8][2] = (c < 4) ? accL : accH;

        const __half* Aw = Ah + (warp_m * 64) * LDKH;
        const __half* Bw = (const __half*)(smem + (c % 3) * STAGE_BYTES
                             + A_STAGE_BYTES) + (warp_n * 64) * LDKH;
#pragma unroll
        for (int ks = 0; ks < 2; ks++) {
            const int kk = ks * 16;
            uint32_t af[4][4];
#pragma unroll
            for (int mi = 0; mi < 4; mi++) {
                int r = mi * 16 + g;
                af[mi][0] = *(const uint32_t*)&Aw[ r      * LDKH + kk + 2 * t    ];
                af[mi][1] = *(const uint32_t*)&Aw[(r + 8) * LDKH + kk + 2 * t    ];
                af[mi][2] = *(const uint32_t*)&Aw[ r      * LDKH + kk + 2 * t + 8];
                af[mi][3] = *(const uint32_t*)&Aw[(r + 8) * LDKH + kk + 2 * t + 8];
            }
            uint32_t bf[8][2];
#pragma unroll
            for (int ni = 0; ni < 8; ni++) {
                int n = ni * 8 + g;
                bf[ni][0] = *(const uint32_t*)&Bw[n * LDKH + kk + 2 * t    ];
                bf[ni][1] = *(const uint32_t*)&Bw[n * LDKH + kk + 2 * t + 8];
            }
#pragma unroll
            for (int mi = 0; mi < 4; mi++)
#pragma unroll
                for (int ni = 0; ni < 8; ni++)
                    mma_f16acc(acc[mi][ni], af[mi], bf[ni]);
        }
    }

    // ---------------- stats: column sums/sumsq -> global atomics -------------
    float* gs = &g_sum  [b * FOUT];
    float* gq = &g_sumsq[b * FOUT];
#pragma unroll
    for (int ni = 0; ni < 8; ni++) {
        const int cc = warp_n * 64 + ni * 8 + 2 * t;
        const float b0v = __ldg(&bias[cc]);
        const float b1v = __ldg(&bias[cc + 1]);
        float s0 = 0.f, s1 = 0.f, q0 = 0.f, q1 = 0.f;
#pragma unroll
        for (int mi = 0; mi < 4; mi++) {
            float2 l0 = __half22float2(*(__half2*)&accL[mi][ni][0]);
            float2 l1 = __half22float2(*(__half2*)&accL[mi][ni][1]);
            float2 h0 = __half22float2(*(__half2*)&accH[mi][ni][0]);
            float2 h1 = __half22float2(*(__half2*)&accH[mi][ni][1]);
            float v0 = l0.x + h0.x + b0v;
            float v1 = l0.y + h0.y + b1v;
            float v2 = l1.x + h1.x + b0v;
            float v3 = l1.y + h1.y + b1v;
            s0 += v0 + v2;  s1 += v1 + v3;
            q0 += v0 * v0 + v2 * v2;
            q1 += v1 * v1 + v3 * v3;
        }
#pragma unroll
        for (int m = 4; m <= 16; m <<= 1) {
            s0 += __shfl_xor_sync(0xFFFFFFFF, s0, m);
            s1 += __shfl_xor_sync(0xFFFFFFFF, s1, m);
            q0 += __shfl_xor_sync(0xFFFFFFFF, q0, m);
            q1 += __shfl_xor_sync(0xFFFFFFFF, q1, m);
        }
        if (lane < 4) {
            atomicAdd(&gs[cc], s0);  atomicAdd(&gs[cc + 1], s1);
            atomicAdd(&gq[cc], q0);  atomicAdd(&gq[cc + 1], q1);
        }
    }

    // ---------------- per-batch spin barrier ---------------------------------
    __threadfence();
    __syncthreads();
    if (tid == 0) {
        atomicAdd(&g_count[b], 1);
        while (atomicAdd(&g_count[b], 0) < CTAS_PER_BATCH)
            __nanosleep(100);
    }
    __syncthreads();
    __threadfence();

    // ---------------- normalize from registers, streaming stores -------------
    const float invN = 1.0f / (float)NTOK;
    float* obase = out + ((size_t)b * NTOK + m0) * FOUT;

#pragma unroll
    for (int ni = 0; ni < 8; ni++) {
        const int cc = warp_n * 64 + ni * 8 + 2 * t;
        const float b0v = __ldg(&bias[cc]);
        const float b1v = __ldg(&bias[cc + 1]);
        float2 sv, qv;
        asm volatile("ld.global.cg.v2.f32 {%0, %1}, [%2];"
                     : "=f"(sv.x), "=f"(sv.y) : "l"(&gs[cc]));
        asm volatile("ld.global.cg.v2.f32 {%0, %1}, [%2];"
                     : "=f"(qv.x), "=f"(qv.y) : "l"(&gq[cc]));
        float mean0 = sv.x * invN;
        float mean1 = sv.y * invN;
        float var0  = fmaxf(qv.x * invN - mean0 * mean0, 0.0f);
        float var1  = fmaxf(qv.y * invN - mean1 * mean1, 0.0f);
        float sc0 = __ldg(&gamma[cc])     * rsqrtf(var0 + EPSBN);
        float sc1 = __ldg(&gamma[cc + 1]) * rsqrtf(var1 + EPSBN);
        float sh0 = __ldg(&beta[cc])     - mean0 * sc0;
        float sh1 = __ldg(&beta[cc + 1]) - mean1 * sc1;
#pragma unroll
        for (int mi = 0; mi < 4; mi++) {
            int r = warp_m * 64 + mi * 16 + g;
            float2 l0 = __half22float2(*(__half2*)&accL[mi][ni][0]);
            float2 l1 = __half22float2(*(__half2*)&accL[mi][ni][1]);
            float2 h0 = __half22float2(*(__half2*)&accH[mi][ni][0]);
            float2 h1 = __half22float2(*(__half2*)&accH[mi][ni][1]);
            float v0 = (l0.x + h0.x + b0v) * sc0 + sh0;
            float v1 = (l0.y + h0.y + b1v) * sc1 + sh1;
            float v2 = (l1.x + h1.x + b0v) * sc0 + sh0;
            float v3 = (l1.y + h1.y + b1v) * sc1 + sh1;
            stcs2(obase + (size_t)r * FOUT + cc,       v0, v1);
            stcs2(obase + (size_t)(r + 8) * FOUT + cc, v2, v3);
        }
    }
}

// ---------------------------------------------------------------------------
extern "C" void kernel_launch(void* const* d_in, const int* in_sizes, int n_in,
                              void* d_out, int out_size)
{
    const float* x     = (const float*)d_in[0];
    const float* W     = (const float*)d_in[1];
    const float* bias  = (const float*)d_in[2];
    const float* gamma = (const float*)d_in[3];
    const float* beta  = (const float*)d_in[4];
    float* out = (float*)d_out;

    cudaFuncSetAttribute(gemm_bn_kernel,
                         cudaFuncAttributeMaxDynamicSharedMemorySize,
                         SMEM_ALLOC);

    prep_kernel<<<FOUT * FIN / 2 / 256, 256>>>(W);
    gemm_bn_kernel<<<BATCH * CTAS_PER_BATCH, THREADS, SMEM_ALLOC>>>(
        x, bias, gamma, beta, out);
}